// round 8
// baseline (speedup 1.0000x reference)
#include <cuda_runtime.h>
#include <cuda_fp16.h>

#define N_USER    50000
#define N_ITEM    10000
#define NUM_NODES 60000
#define EMB_D     64
#define N_EDGES   2000000
#define N_GROUPS4 (N_EDGES / 4)   // 4 edges per 16-lane group

// Table scale: keeps fp16 products in normal range.
#define TBL_SCALE      512.0f
#define INV_TBL_SCALE2 (1.0f / (512.0f * 512.0f))   // 2^-18

// Fused, pre-scaled node table in fp16: row = 64 half = 128 B (one L1 line).
__device__ __half g_nodes[NUM_NODES * EMB_D];

// Phase 1: build fused node table (fp32 math, fp16 store, x512 pre-scale).
__global__ void build_nodes_kernel(const float* __restrict__ user_emb,
                                   const float* __restrict__ item_emb,
                                   const float* __restrict__ tag_emb,
                                   const float* __restrict__ testid_emb,
                                   const float* __restrict__ bigcat_emb,
                                   const float* __restrict__ daydiff_emb,
                                   const int*  __restrict__ item_tags,
                                   const int*  __restrict__ item_testids,
                                   const int*  __restrict__ item_bigcat,
                                   const int*  __restrict__ user_daydiff) {
    unsigned int t = blockIdx.x * blockDim.x + threadIdx.x;
    unsigned int node = t >> 4;
    unsigned int sub  = t & 15u;
    if (node >= NUM_NODES) return;
    unsigned int off = sub * 4u;

    const float alpha = 1.0f / 3.0f;
    float4 r;
    if (node < N_USER) {
        const float s = 0.5f * alpha * TBL_SCALE;
        int dd = user_daydiff[node];
        float4 u = *(const float4*)(user_emb    + (size_t)node * EMB_D + off);
        float4 d = *(const float4*)(daydiff_emb + (size_t)dd   * EMB_D + off);
        r.x = (u.x + d.x) * s;
        r.y = (u.y + d.y) * s;
        r.z = (u.z + d.z) * s;
        r.w = (u.w + d.w) * s;
    } else {
        const float s = 0.25f * alpha * TBL_SCALE;
        unsigned int it = node - N_USER;
        int tg = item_tags[it];
        int ts = item_testids[it];
        int bc = item_bigcat[it];
        float4 a = *(const float4*)(item_emb   + (size_t)it * EMB_D + off);
        float4 b = *(const float4*)(tag_emb    + (size_t)tg * EMB_D + off);
        float4 c = *(const float4*)(testid_emb + (size_t)ts * EMB_D + off);
        float4 e = *(const float4*)(bigcat_emb + (size_t)bc * EMB_D + off);
        r.x = (a.x + b.x + c.x + e.x) * s;
        r.y = (a.y + b.y + c.y + e.y) * s;
        r.z = (a.z + b.z + c.z + e.z) * s;
        r.w = (a.w + b.w + c.w + e.w) * s;
    }
    __half2 h0 = __floats2half2_rn(r.x, r.y);
    __half2 h1 = __floats2half2_rn(r.z, r.w);
    uint2 packed;
    packed.x = *(const unsigned int*)&h0;
    packed.y = *(const unsigned int*)&h1;
    *(uint2*)((char*)g_nodes + (size_t)node * 128u + sub * 8u) = packed;
}

__device__ __forceinline__ __half2 shfl_h2(__half2 v, int ofs) {
    unsigned int u = *(unsigned int*)&v;
    u = __shfl_xor_sync(0xffffffffu, u, ofs);
    return *(__half2*)&u;
}

// 4-half partial dot from two uint2s: 2 HMUL2 + 1 HADD2.
__device__ __forceinline__ __half2 pdot2(uint2 a, uint2 b) {
    __half2 a0 = *(__half2*)&a.x, a1 = *(__half2*)&a.y;
    __half2 b0 = *(__half2*)&b.x, b1 = *(__half2*)&b.y;
    return __hadd2(__hmul2(a0, b0), __hmul2(a1, b1));
}

// Phase 2: 4 edges per 16-lane group. Each gather is an LDG.64 with 16 lanes
// covering ONE 128B row (warp instr = 2 rows = 2 wavefronts -> 1.54 cyc/row
// vs LDG.128's 1.80). 8 independent gathers per thread; 5-SHFL value-halving
// reduction; lanes with sub%4==0 write edges (2*bit3+bit2).
__global__ __launch_bounds__(256) void edge_dot_kernel(
        const int4* __restrict__ src4,
        const int4* __restrict__ dst4,
        float* __restrict__ out) {
    unsigned int t = blockIdx.x * blockDim.x + threadIdx.x;
    unsigned int g   = t >> 4;
    unsigned int sub = t & 15u;
    if (g >= N_GROUPS4) return;

    int4 s = src4[g];   // same addr across the 16-lane group
    int4 d = dst4[g];

    const uint2* np = (const uint2*)g_nodes + sub;   // row = 16 uint2

    uint2 a0 = np[(unsigned)s.x * 16u];
    uint2 b0 = np[(unsigned)d.x * 16u];
    uint2 a1 = np[(unsigned)s.y * 16u];
    uint2 b1 = np[(unsigned)d.y * 16u];
    uint2 a2 = np[(unsigned)s.z * 16u];
    uint2 b2 = np[(unsigned)d.z * 16u];
    uint2 a3 = np[(unsigned)s.w * 16u];
    uint2 b3 = np[(unsigned)d.w * 16u];

    __half2 v0 = pdot2(a0, b0);
    __half2 v1 = pdot2(a1, b1);
    __half2 v2 = pdot2(a2, b2);
    __half2 v3 = pdot2(a3, b3);

    bool bit3 = (sub & 8u) != 0u;
    bool bit2 = (sub & 4u) != 0u;

    // Stage 1 (xor 8): 4 -> 2 values. Lo lanes keep edges {0,1}, hi keep {2,3}.
    __half2 q0 = bit3 ? v0 : v2;
    __half2 q1 = bit3 ? v1 : v3;
    __half2 w0 = __hadd2(bit3 ? v2 : v0, shfl_h2(q0, 8));
    __half2 w1 = __hadd2(bit3 ? v3 : v1, shfl_h2(q1, 8));

    // Stage 2 (xor 4): 2 -> 1. Lane owns edge e = 2*bit3 + bit2.
    __half2 q2 = bit2 ? w0 : w1;
    __half2 x  = __hadd2(bit2 ? w1 : w0, shfl_h2(q2, 4));

    // Stages 3,4 (xor 2, xor 1): duplicate-sums across remaining 4 lanes.
    __half2 y = __hadd2(x, shfl_h2(x, 2));
    __half2 z = __hadd2(y, shfl_h2(y, 1));

    if ((sub & 3u) == 0u) {
        unsigned int e = ((sub >> 3) << 1) | ((sub >> 2) & 1u);
        float2 f = __half22float2(z);
        out[g * 4u + e] = (f.x + f.y) * INV_TBL_SCALE2;
    }
}

extern "C" void kernel_launch(void* const* d_in, const int* in_sizes, int n_in,
                              void* d_out, int out_size) {
    const float* user_emb     = (const float*)d_in[0];
    const float* item_emb     = (const float*)d_in[1];
    const float* tag_emb      = (const float*)d_in[2];
    const float* testid_emb   = (const float*)d_in[3];
    const float* bigcat_emb   = (const float*)d_in[4];
    const float* daydiff_emb  = (const float*)d_in[5];
    const int*   edge_index   = (const int*)d_in[6];   // [2, N_EDGES] int32
    const int*   item_tags    = (const int*)d_in[7];
    const int*   item_testids = (const int*)d_in[8];
    const int*   item_bigcat  = (const int*)d_in[9];
    const int*   user_daydiff = (const int*)d_in[10];

    // Phase 1: 60000 nodes * 16 threads
    {
        unsigned int total = NUM_NODES * 16u;
        unsigned int threads = 256;
        unsigned int blocks = (total + threads - 1) / threads;
        build_nodes_kernel<<<blocks, threads>>>(user_emb, item_emb, tag_emb,
                                                testid_emb, bigcat_emb, daydiff_emb,
                                                item_tags, item_testids, item_bigcat,
                                                user_daydiff);
    }

    // Phase 2: 500K groups * 16 threads = 8M threads
    {
        const int4* src4 = (const int4*)edge_index;
        const int4* dst4 = (const int4*)(edge_index + N_EDGES);
        unsigned int total = N_GROUPS4 * 16u;
        unsigned int threads = 256;
        unsigned int blocks = (total + threads - 1) / threads;
        edge_dot_kernel<<<blocks, threads>>>(src4, dst4, (float*)d_out);
    }
}